// round 16
// baseline (speedup 1.0000x reference)
#include <cuda_runtime.h>
#include <math.h>

#define NS        100
#define NPIX      (NS * NS)
#define PARTS     8
#define MAXPARTS  16
#define BLOCK     256
#define U         8
#define NCTA      740      // 148 SMs * 5 CTAs/SM -> one wave
#define INF_F     1000000000.0f
#define MU_F      1e-8f
#define SAFE_THR  0.05f

__device__ __forceinline__ float fsqrt_approx(float x) {
    float r; asm("sqrt.approx.f32 %0, %1;" : "=f"(r) : "f"(x)); return r;
}
__device__ __forceinline__ float frcp_approx(float x) {
    float r; asm("rcp.approx.f32 %0, %1;" : "=f"(r) : "f"(x)); return r;
}

__global__ __launch_bounds__(BLOCK, 5)
void pc_kernel(const float* __restrict__ seg_maps,      // (B,100,100)
               const float* __restrict__ seg_map_paras, // (B,6)
               const float* __restrict__ trajectories,  // (B,8,2)
               const float* __restrict__ current_pos,   // (B,1,2)
               float* __restrict__ out,                 // (B,16,3)
               int B)
{
    const int tid  = threadIdx.x;
    const int lane = tid & 31;

    __shared__ float sraw[12];
    __shared__ int   smin[PARTS];

    for (int b = blockIdx.x; b < B; b += gridDim.x) {

        // parallel preamble: one memory round, 12 scalars
        if (tid < 6)       sraw[tid] = __ldg(seg_map_paras + b * 6 + tid);
        else if (tid < 8)  sraw[tid] = __ldg(trajectories + b * 16 + (tid - 6));       // tr0
        else if (tid < 10) sraw[tid] = __ldg(trajectories + b * 16 + 14 + (tid - 8));  // tr7
        else if (tid < 12) sraw[tid] = __ldg(current_pos + b * 2 + (tid - 10));        // c
        if (tid < PARTS)   smin[tid] = __float_as_int(INF_F);
        __syncthreads();

        // redundant per-thread derivation (ALU only, division-free)
        const float W0 = sraw[0], W1 = sraw[1], b0 = sraw[2], b1 = sraw[3];
        const bool  swp = (sraw[4] == 1.0f);
        const float mvx = sraw[8] - sraw[6];
        const float mvy = sraw[9] - sraw[7];
        const float ml  = sqrtf(mvx * mvx + mvy * mvy);
        const float r   = 2.0f * ml;
        const float cx  = sraw[10], cy = sraw[11];

        const float invW0 = 1.0f / W0;
        const float invW1 = 1.0f / W1;
        const float offI = -b0 * invW0 - (swp ? cy : cx);
        const float offJ = -b1 * invW1 - (swp ? cx : cy);

        // conservative pixel bbox (+/-1 margin); extra pixels are rejected by
        // the exact dd<=r2 test, so widening never changes the result.
        int il = (int)floorf((-r - offI) * W0) - 1;
        int ih = (int)ceilf (( r - offI) * W0) + 1;
        int jl = (int)floorf((-r - offJ) * W1) - 1;
        int jh = (int)ceilf (( r - offJ) * W1) + 1;
        il = max(il, 0);  ih = min(ih, NS - 1);
        jl = max(jl, 0);  jh = min(jh, NS - 1);

        const int Wd = jh - jl + 1;
        const int Hd = ih - il + 1;
        const int tot = (Wd > 0 && Hd > 0) ? Wd * Hd : 0;

        // exact row split without a divide: (idx+0.5)/Wd lies strictly inside
        // (qi, qi+1); float error << 0.5/Wd, so floor is exact.
        const float rWd = 1.0f / (float)max(Wd, 1);
        const float half_rWd = 0.5f * rWd;

        const float offIp = fmaf((float)il, invW0, offI);
        const float offJp = fmaf((float)jl, invW1, offJ);
        const float r2 = r * r;
        const float* base = seg_maps + (size_t)b * NPIX + (il * NS + jl);
        const int rowadj = NS - Wd;                 // addr = idx + qi*rowadj

        float lmin[PARTS];
#pragma unroll
        for (int p = 0; p < PARTS; ++p) lmin[p] = INF_F;

        for (int lo = 0; lo < tot; lo += BLOCK * U) {
            float mv[U];
#pragma unroll
            for (int k = 0; k < U; ++k) {
                int idx = lo + k * BLOCK + tid;
                int cidx = (idx < tot) ? idx : 0;   // clamped, in-bounds
                int qi  = __float2int_rd(fmaf((float)cidx, rWd, half_rWd));
                mv[k]   = (idx < tot) ? __ldg(base + cidx + qi * rowadj) : 0.0f;
            }
#pragma unroll
            for (int k = 0; k < U; ++k) {
                int idx = lo + k * BLOCK + tid;
                int cidx = (idx < tot) ? idx : 0;
                int qi  = __float2int_rd(fmaf((float)cidx, rWd, half_rWd));
                int qj  = cidx - qi * Wd;
                float m    = mv[k];
                float dirI = fmaf((float)qi, invW0, offIp);
                float dirJ = fmaf((float)qj, invW1, offJp);
                float dd   = fmaf(dirJ, dirJ, dirI * dirI);
                if (idx < tot && m > SAFE_THR && dd <= r2) {
                    float dist = fsqrt_approx(dd);
                    float eq   = (dist + MU_F) * frcp_approx(m + MU_F);
                    float sv = swp ? dirJ : dirI;   // angle = atan2(sv, cv)
                    float cv = swp ? dirI : dirJ;
                    // branchless octant (matches reference <=,>= boundaries)
                    int ss  = (int)(__float_as_uint(sv) >> 31);
                    int scn = (int)(__float_as_uint(cv) >> 31);
                    int odd = ss ^ scn;
                    float as = fabsf(sv), ac = fabsf(cv);
                    int low = odd ? (as < ac) : (as > ac);
                    int bin = (ss << 2) | (odd << 1) | low;
#pragma unroll
                    for (int p = 0; p < PARTS; ++p)
                        lmin[p] = (bin == p) ? fminf(lmin[p], eq) : lmin[p];
                }
            }
        }

        // one-instruction warp reduction per bin (REDUX.SYNC.MIN.U32);
        // lmin >= 0 so uint ordering == float ordering
#pragma unroll
        for (int p = 0; p < PARTS; ++p) {
            unsigned u = __reduce_min_sync(0xffffffffu, __float_as_uint(lmin[p]));
            if (lane == 0)
                atomicMin(&smin[p], (int)u);
        }
        __syncthreads();

        // coalesced epilogue: 12 threads x one float4 = 48 floats (B,16,3).
        // value v in [0,48): part = v/3, comp = v%3.
        if (tid < 12) {
            float4 o4;
            float* v4 = &o4.x;
#pragma unroll
            for (int c = 0; c < 4; ++c) {
                int v    = tid * 4 + c;
                int part = v / 3;            // compile-time-strength-reduced
                int comp = v - part * 3;
                float val = 0.0f;
                if (part < PARTS) {
                    float md = fminf(__int_as_float(smin[part]), INF_F);
                    if (md < INF_F) {
                        if (comp == 0)      val = ml;
                        else if (comp == 1) val = md;
                        else val = (float)(6.283185307179586 * ((double)part + 0.5) / 8.0);
                    }
                }
                v4[c] = val;
            }
            *((float4*)(out + (size_t)b * (MAXPARTS * 3)) + tid) = o4;
        }
        __syncthreads();   // protect sraw/smin reuse across batches
    }
}

extern "C" void kernel_launch(void* const* d_in, const int* in_sizes, int n_in,
                              void* d_out, int out_size)
{
    const float* seg_maps      = (const float*)d_in[0];
    const float* seg_map_paras = (const float*)d_in[1];
    const float* trajectories  = (const float*)d_in[2];
    const float* current_pos   = (const float*)d_in[3];
    float* out = (float*)d_out;

    int B = in_sizes[0] / NPIX;   // 1024
    int grid = (B < NCTA) ? B : NCTA;
    pc_kernel<<<grid, BLOCK>>>(seg_maps, seg_map_paras, trajectories,
                               current_pos, out, B);
}

// round 17
// speedup vs baseline: 1.3208x; 1.3208x over previous
#include <cuda_runtime.h>
#include <math.h>

#define NS        100
#define NPIX      (NS * NS)
#define PARTS     8
#define MAXPARTS  16
#define BLOCK     256
#define U         8
#define NCTA      740      // 148 SMs * 5 CTAs/SM -> one wave
#define INF_F     1000000000.0f
#define MU_F      1e-8f
#define SAFE_THR  0.05f

__device__ __forceinline__ float fsqrt_approx(float x) {
    float r; asm("sqrt.approx.f32 %0, %1;" : "=f"(r) : "f"(x)); return r;
}
__device__ __forceinline__ float frcp_approx(float x) {
    float r; asm("rcp.approx.f32 %0, %1;" : "=f"(r) : "f"(x)); return r;
}

__global__ __launch_bounds__(BLOCK, 5)
void pc_kernel(const float* __restrict__ seg_maps,      // (B,100,100)
               const float* __restrict__ seg_map_paras, // (B,6)
               const float* __restrict__ trajectories,  // (B,8,2)
               const float* __restrict__ current_pos,   // (B,1,2)
               float* __restrict__ out,                 // (B,16,3)
               int B)
{
    const int tid  = threadIdx.x;
    const int lane = tid & 31;

    __shared__ float sraw[12];
    __shared__ int   smin[PARTS];

    for (int b = blockIdx.x; b < B; b += gridDim.x) {

        // parallel preamble: one memory round, 12 scalars
        if (tid < 6)       sraw[tid] = __ldg(seg_map_paras + b * 6 + tid);
        else if (tid < 8)  sraw[tid] = __ldg(trajectories + b * 16 + (tid - 6));       // tr0x, tr0y
        else if (tid < 10) sraw[tid] = __ldg(trajectories + b * 16 + 14 + (tid - 8));  // tr7x, tr7y
        else if (tid < 12) sraw[tid] = __ldg(current_pos + b * 2 + (tid - 10));        // cx, cy
        if (tid < PARTS)   smin[tid] = __float_as_int(INF_F);
        __syncthreads();

        // redundant per-thread derivation (ALU only, no serial section)
        const float W0 = sraw[0], W1 = sraw[1], b0 = sraw[2], b1 = sraw[3];
        const bool  swp = (sraw[4] == 1.0f);
        const float mvx = sraw[8] - sraw[6];
        const float mvy = sraw[9] - sraw[7];
        const float ml  = sqrtf(mvx * mvx + mvy * mvy);
        const float r   = 2.0f * ml;
        const float cx  = sraw[10], cy = sraw[11];

        const float invW0 = 1.0f / W0;
        const float invW1 = 1.0f / W1;
        const float offI = -b0 * invW0 - (swp ? cy : cx);
        const float offJ = -b1 * invW1 - (swp ? cx : cy);

        // conservative pixel-space bbox of the valid disk (+/-1 px margin);
        // scanning extra pixels never changes the result (exact dd<=r2 test).
        int il = (int)floorf((-r - offI) * W0) - 1;
        int ih = (int)ceilf (( r - offI) * W0) + 1;
        int jl = (int)floorf((-r - offJ) * W1) - 1;
        int jh = (int)ceilf (( r - offJ) * W1) + 1;
        il = max(il, 0);  ih = min(ih, NS - 1);
        jl = max(jl, 0);  jh = min(jh, NS - 1);
        if (jh == jl) { if (jh < NS - 1) ++jh; else --jl; }   // Wd >= 2

        const int Wd = jh - jl + 1;
        const int Hd = ih - il + 1;
        const int tot = (Wd > 0 && Hd > 0) ? Wd * Hd : 0;

        // exact division by Wd for idx <= 10000: qi = umulhi(idx, M)
        const unsigned M = ((2097152u + (unsigned)Wd - 1u) / (unsigned)Wd) << 11;

        const float offIp = fmaf((float)il, invW0, offI);
        const float offJp = fmaf((float)jl, invW1, offJ);
        const float r2 = r * r;
        const float* base = seg_maps + (size_t)b * NPIX + (il * NS + jl);
        const int rowadj = NS - Wd;

        float lmin[PARTS];
#pragma unroll
        for (int p = 0; p < PARTS; ++p) lmin[p] = INF_F;

        for (int lo = 0; lo < tot; lo += BLOCK * U) {
            float mv[U];
#pragma unroll
            for (int k = 0; k < U; ++k) {
                int idx = lo + k * BLOCK + tid;
                int cidx = (idx < tot) ? idx : 0;           // clamped, in-bounds
                int qi  = (int)__umulhi((unsigned)cidx, M); // exact cidx / Wd
                mv[k]   = (idx < tot) ? __ldg(base + cidx + qi * rowadj) : 0.0f;
            }
#pragma unroll
            for (int k = 0; k < U; ++k) {
                int idx = lo + k * BLOCK + tid;
                int cidx = (idx < tot) ? idx : 0;
                int qi = (int)__umulhi((unsigned)cidx, M);
                int qj = cidx - qi * Wd;
                float m    = mv[k];
                float dirI = fmaf((float)qi, invW0, offIp);
                float dirJ = fmaf((float)qj, invW1, offJp);
                float dd   = fmaf(dirJ, dirJ, dirI * dirI);
                if (idx < tot && m > SAFE_THR && dd <= r2) {
                    float dist = fsqrt_approx(dd);
                    float eq   = (dist + MU_F) * frcp_approx(m + MU_F);
                    float sv = swp ? dirJ : dirI;   // angle = atan2(sv, cv)
                    float cv = swp ? dirI : dirJ;
                    int bin;
                    if (sv >= 0.0f) {
                        if (cv >= 0.0f) bin = (sv <= cv)  ? 0 : 1;
                        else            bin = (sv >= -cv) ? 2 : 3;
                    } else {
                        if (cv <= 0.0f) bin = (-sv <= -cv) ? 4 : 5;
                        else            bin = (-sv >= cv)  ? 6 : 7;
                    }
#pragma unroll
                    for (int p = 0; p < PARTS; ++p)
                        lmin[p] = (bin == p) ? fminf(lmin[p], eq) : lmin[p];
                }
            }
        }

        // warp min-reduce per bin, then one smem atomic per warp per bin
#pragma unroll
        for (int p = 0; p < PARTS; ++p) {
            float v = lmin[p];
#pragma unroll
            for (int o = 16; o > 0; o >>= 1)
                v = fminf(v, __shfl_xor_sync(0xffffffffu, v, o));
            if (lane == 0)
                atomicMin(&smin[p], __float_as_int(v));  // vals >= 0: int order == float order
        }
        __syncthreads();

        if (tid < MAXPARTS) {
            float fv = 0.0f, fd = 0.0f, fr = 0.0f;
            if (tid < PARTS) {
                float md = fminf(__int_as_float(smin[tid]), INF_F);
                if (md < INF_F) {
                    fv = ml;
                    fd = md;
                    fr = (float)(6.283185307179586 * ((double)tid + 0.5) / 8.0);
                }
            }
            float* o = out + (size_t)b * (MAXPARTS * 3) + tid * 3;
            o[0] = fv; o[1] = fd; o[2] = fr;
        }
        __syncthreads();   // protect sraw/smin reuse in next batch
    }
}

extern "C" void kernel_launch(void* const* d_in, const int* in_sizes, int n_in,
                              void* d_out, int out_size)
{
    const float* seg_maps      = (const float*)d_in[0];
    const float* seg_map_paras = (const float*)d_in[1];
    const float* trajectories  = (const float*)d_in[2];
    const float* current_pos   = (const float*)d_in[3];
    float* out = (float*)d_out;

    int B = in_sizes[0] / NPIX;   // 1024
    int grid = (B < NCTA) ? B : NCTA;
    pc_kernel<<<grid, BLOCK>>>(seg_maps, seg_map_paras, trajectories,
                               current_pos, out, B);
}